// round 3
// baseline (speedup 1.0000x reference)
#include <cuda_runtime.h>
#include <math.h>

#define Nn 60000
#define Mm 12
#define F0k 92
#define FBk 41
#define Ff 64
#define Hh 128
#define NCc 2000
#define F2 128
#define NM (Nn*Mm)

// ---------------- scratch (static device memory, no allocs) ----------------
__device__ float g_x[Nn*Ff];
__device__ float g_P[Nn*256];
__device__ float g_gated[(size_t)NM*F2];
__device__ float g_summed[Nn*Ff];
__device__ double g_stats1[2*F2];
__device__ double g_stats2[2*Ff];
__device__ float g_sc1[F2], g_sh1[F2];
__device__ float g_sc2[Ff], g_sh2[Ff];
__device__ float g_crys[NCc*Ff];
__device__ float g_cnt[NCc];

__device__ __forceinline__ float sp(float x){
    return fmaxf(x, 0.f) + __logf(1.f + __expf(-fabsf(x)));
}
__device__ __forceinline__ float sg(float x){
    return __fdividef(1.f, 1.f + __expf(-x));
}

// ---------------- embedding ----------------
__global__ void k_emb(const float* __restrict__ af, const float* __restrict__ W,
                      const float* __restrict__ b){
    __shared__ float s_af[8][F0k];
    int base = blockIdx.x * 8;
    int tid = threadIdx.x;                    // 512
    for(int idx = tid; idx < 8*F0k; idx += 512){
        int a = idx / F0k, k = idx % F0k;
        s_af[a][k] = af[(base+a)*F0k + k];
    }
    __syncthreads();
    int a = tid >> 6, f = tid & 63;
    float acc = b[f];
    #pragma unroll 4
    for(int k = 0; k < F0k; k++) acc += s_af[a][k] * W[k*Ff + f];
    g_x[(base+a)*Ff + f] = acc;
}

__global__ void k_zero_stats(){
    int t = threadIdx.x;
    g_stats1[t] = 0.0;
    if(t < 2*Ff) g_stats2[t] = 0.0;
}

// ---------------- P = x @ [W1 | W2] (128x128 tile, 512 thr, 4x8/thread) ----
__global__ void __launch_bounds__(512,2) k_P(const float* __restrict__ Wf){
    __shared__ __align__(16) float Ws[32][128];
    __shared__ __align__(16) float Xt[32][132];
    int half = blockIdx.y;
    int base = blockIdx.x * 128;
    int rem  = Nn - base;
    int tid  = threadIdx.x;                   // 512
    int tx = tid & 15, ty = tid >> 4;         // ty 0..31

    float acc[4][8];
    #pragma unroll
    for(int r=0;r<4;r++)
        #pragma unroll
        for(int c=0;c<8;c++) acc[r][c]=0.f;

    for(int kc = 0; kc < 2; kc++){
        for(int i2 = tid; i2 < 32*128; i2 += 512){
            int kk = i2 >> 7, j = i2 & 127;
            Ws[kk][j] = Wf[(half*64 + kc*32 + kk)*128 + j];
        }
        for(int i2 = tid; i2 < 32*128; i2 += 512){
            int a = i2 >> 5, kk = i2 & 31;
            int atom = base + a; if(atom >= Nn) atom = Nn-1;
            Xt[kk][a] = g_x[atom*64 + kc*32 + kk];
        }
        __syncthreads();
        #pragma unroll 1
        for(int k = 0; k < 32; k++){
            float4 a0 = *(const float4*)&Xt[k][ty*4];
            float4 b0 = *(const float4*)&Ws[k][tx*4];
            float4 b1 = *(const float4*)&Ws[k][64 + tx*4];
            float av[4] = {a0.x,a0.y,a0.z,a0.w};
            float bv[8] = {b0.x,b0.y,b0.z,b0.w,b1.x,b1.y,b1.z,b1.w};
            #pragma unroll
            for(int r=0;r<4;r++)
                #pragma unroll
                for(int c=0;c<8;c++) acc[r][c] += av[r]*bv[c];
        }
        __syncthreads();
    }
    #pragma unroll
    for(int r=0;r<4;r++){
        int row = ty*4 + r;
        if(row < rem){
            float* dst = g_P + (size_t)(base+row)*256 + half*128;
            *(float4*)&dst[tx*4]    = make_float4(acc[r][0],acc[r][1],acc[r][2],acc[r][3]);
            *(float4*)&dst[64+tx*4] = make_float4(acc[r][4],acc[r][5],acc[r][6],acc[r][7]);
        }
    }
}

// ------- edge GEMM + P adds + bias + BN1 stats (512 thr, 4x8/thread) -------
__global__ void __launch_bounds__(512,2) k_Q(const float* __restrict__ nbr,
                    const int* __restrict__ idx,
                    const float* __restrict__ Wf, const float* __restrict__ bias){
    __shared__ __align__(16) float Ws[41][128];
    __shared__ __align__(16) float At[41][132];
    __shared__ float reds[128], redss[128];
    int tid = threadIdx.x;                    // 512
    int row0 = blockIdx.x * 128;
    int tx = tid & 15, ty = tid >> 4;         // ty 0..31
    const float* W3 = Wf + 128*128;

    for(int i2 = tid; i2 < 41*128; i2 += 512){
        int k = i2 >> 7, j = i2 & 127;
        Ws[k][j] = W3[k*128 + j];
    }
    for(int i2 = tid; i2 < 128*41; i2 += 512){
        int r = i2 / 41, k = i2 % 41;
        At[k][r] = nbr[(size_t)(row0 + r)*41 + k];
    }
    if(tid < 128){ reds[tid] = 0.f; redss[tid] = 0.f; }
    __syncthreads();

    float acc[4][8];
    #pragma unroll
    for(int r=0;r<4;r++)
        #pragma unroll
        for(int c=0;c<8;c++) acc[r][c]=0.f;

    #pragma unroll 1
    for(int k = 0; k < 41; k++){
        float4 a0 = *(const float4*)&At[k][ty*4];
        float4 b0 = *(const float4*)&Ws[k][tx*4];
        float4 b1 = *(const float4*)&Ws[k][64 + tx*4];
        float av[4] = {a0.x,a0.y,a0.z,a0.w};
        float bv[8] = {b0.x,b0.y,b0.z,b0.w,b1.x,b1.y,b1.z,b1.w};
        #pragma unroll
        for(int r=0;r<4;r++)
            #pragma unroll
            for(int c=0;c<8;c++) acc[r][c] += av[r]*bv[c];
    }
    __syncthreads();

    // overlay epilogue data in At storage
    float (*sP1)[128] = (float(*)[128])&At[0][0];        // 12*128 floats
    int*   sIdx       = (int*)(&At[0][0] + 12*128);      // 128 ints
    int a0atom = row0 / Mm;
    for(int j = tid; j < 12*128; j += 512){
        int at = j >> 7, col = j & 127;
        int atom = a0atom + at; if(atom >= Nn) atom = Nn-1;
        sP1[at][col] = g_P[(size_t)atom*256 + col];
    }
    if(tid < 128) sIdx[tid] = idx[row0 + tid];
    __syncthreads();

    float4 bb0 = *(const float4*)&bias[tx*4];
    float4 bb1 = *(const float4*)&bias[64 + tx*4];
    float bj[8] = {bb0.x,bb0.y,bb0.z,bb0.w,bb1.x,bb1.y,bb1.z,bb1.w};

    float s[8], ssq[8];
    #pragma unroll
    for(int c=0;c<8;c++){ s[c]=0.f; ssq[c]=0.f; }

    #pragma unroll
    for(int r=0;r<4;r++){
        int row = ty*4 + r;
        int g = row0 + row;
        int irel = (g / Mm) - a0atom;
        int nb = sIdx[row];
        const float* p2p = g_P + (size_t)nb*256 + 128;
        float4 p1a = *(const float4*)&sP1[irel][tx*4];
        float4 p1b = *(const float4*)&sP1[irel][64+tx*4];
        float4 p2a = *(const float4*)&p2p[tx*4];
        float4 p2b = *(const float4*)&p2p[64+tx*4];
        float pv[8] = {p1a.x+p2a.x, p1a.y+p2a.y, p1a.z+p2a.z, p1a.w+p2a.w,
                       p1b.x+p2b.x, p1b.y+p2b.y, p1b.z+p2b.z, p1b.w+p2b.w};
        float out[8];
        #pragma unroll
        for(int c=0;c<8;c++){
            float v = acc[r][c] + bj[c] + pv[c];
            out[c] = v; s[c] += v; ssq[c] += v*v;
        }
        float* dst = g_gated + (size_t)g*128;
        *(float4*)&dst[tx*4]    = make_float4(out[0],out[1],out[2],out[3]);
        *(float4*)&dst[64+tx*4] = make_float4(out[4],out[5],out[6],out[7]);
    }
    #pragma unroll
    for(int c=0;c<8;c++){
        int col = (c<4) ? (tx*4+c) : (64 + tx*4 + (c-4));
        atomicAdd(&reds [col], s[c]);
        atomicAdd(&redss[col], ssq[c]);
    }
    __syncthreads();
    if(tid < 128){
        atomicAdd(&g_stats1[tid],       (double)reds[tid]);
        atomicAdd(&g_stats1[128 + tid], (double)redss[tid]);
    }
}

__global__ void k_fin1(const float* __restrict__ g1, const float* __restrict__ be1){
    int j = threadIdx.x;                      // 128
    double n = (double)NM;
    double mu = g_stats1[j] / n;
    double var = g_stats1[128 + j] / n - mu*mu;
    float r = rsqrtf((float)var + 1e-5f);
    float sc = g1[j] * r;
    g_sc1[j] = sc;
    g_sh1[j] = be1[j] - (float)mu * sc;
}

// ------- BN1 apply + sigmoid*softplus + sum over M + BN2 stats (float4) ----
__global__ void k_B(){
    __shared__ float rs[64], rss[64];
    int tid = threadIdx.x;                    // 256; 32 atoms/block
    int fg = (tid & 15) * 4;
    int s  = tid >> 4;                        // 0..15, 2 atoms each
    int base = blockIdx.x * 32 + s*2;
    if(tid < 64){ rs[tid] = 0.f; rss[tid] = 0.f; }
    float4 scf = *(const float4*)&g_sc1[fg];
    float4 shf = *(const float4*)&g_sh1[fg];
    float4 scc = *(const float4*)&g_sc1[64+fg];
    float4 shc = *(const float4*)&g_sh1[64+fg];
    float sc_f[4] = {scf.x,scf.y,scf.z,scf.w};
    float sh_f[4] = {shf.x,shf.y,shf.z,shf.w};
    float sc_c[4] = {scc.x,scc.y,scc.z,scc.w};
    float sh_c[4] = {shc.x,shc.y,shc.z,shc.w};
    __syncthreads();

    float ts[4] = {0,0,0,0}, tss[4] = {0,0,0,0};
    #pragma unroll
    for(int a = 0; a < 2; a++){
        int i = base + a;
        const float* gp = g_gated + (size_t)i*Mm*F2;
        float acc[4] = {0,0,0,0};
        #pragma unroll
        for(int m = 0; m < Mm; m++){
            float4 vf = *(const float4*)&gp[m*F2 + fg];
            float4 vc = *(const float4*)&gp[m*F2 + 64 + fg];
            float f0[4] = {vf.x,vf.y,vf.z,vf.w};
            float c0[4] = {vc.x,vc.y,vc.z,vc.w};
            #pragma unroll
            for(int c=0;c<4;c++)
                acc[c] += sg(f0[c]*sc_f[c]+sh_f[c]) * sp(c0[c]*sc_c[c]+sh_c[c]);
        }
        *(float4*)&g_summed[i*64 + fg] = make_float4(acc[0],acc[1],acc[2],acc[3]);
        #pragma unroll
        for(int c=0;c<4;c++){ ts[c] += acc[c]; tss[c] += acc[c]*acc[c]; }
    }
    #pragma unroll
    for(int c=0;c<4;c++){
        atomicAdd(&rs [fg+c], ts[c]);
        atomicAdd(&rss[fg+c], tss[c]);
    }
    __syncthreads();
    if(tid < 64){
        atomicAdd(&g_stats2[tid],      (double)rs[tid]);
        atomicAdd(&g_stats2[64 + tid], (double)rss[tid]);
    }
}

__global__ void k_fin2(const float* __restrict__ g2, const float* __restrict__ be2){
    int j = threadIdx.x;                      // 64
    double n = (double)Nn;
    double mu = g_stats2[j] / n;
    double var = g_stats2[64 + j] / n - mu*mu;
    float r = rsqrtf((float)var + 1e-5f);
    float sc = g2[j] * r;
    g_sc2[j] = sc;
    g_sh2[j] = be2[j] - (float)mu * sc;
}

__global__ void k_upd(){
    int id = blockIdx.x*256 + threadIdx.x;    // N*16 threads (float4 each)
    int fg = (id & 15) * 4;
    float4 xv = *(const float4*)&g_x[id*4];
    float4 sv = *(const float4*)&g_summed[id*4];
    float4 sc = *(const float4*)&g_sc2[fg];
    float4 sh = *(const float4*)&g_sh2[fg];
    float4 o;
    o.x = sp(xv.x + sv.x*sc.x + sh.x);
    o.y = sp(xv.y + sv.y*sc.y + sh.y);
    o.z = sp(xv.z + sv.z*sc.z + sh.z);
    o.w = sp(xv.w + sv.w*sc.w + sh.w);
    *(float4*)&g_x[id*4] = o;
}

// ---------------- pooling + head ----------------
__global__ void k_pool_zero(){
    int id = blockIdx.x*256 + threadIdx.x;
    if(id < NCc*Ff) g_crys[id] = 0.f;
    else if(id < NCc*Ff + NCc) g_cnt[id - NCc*Ff] = 0.f;
}

__global__ void k_pool(const int* __restrict__ cidx){
    int id = blockIdx.x*256 + threadIdx.x;    // N*64 threads
    int i = id >> 6, f = id & 63;
    int c = cidx[i];
    atomicAdd(&g_crys[c*64 + f], g_x[id]);
    if(f == 0) atomicAdd(&g_cnt[c], 1.f);
}

__global__ void k_head(const float* __restrict__ W_fc, const float* __restrict__ b_fc,
                       const float* __restrict__ W_out, const float* __restrict__ b_out,
                       float* __restrict__ out){
    __shared__ float t[64];
    __shared__ float hred[128];
    int c = blockIdx.x, th = threadIdx.x;     // 128
    if(th < 64){
        float cn = fmaxf(g_cnt[c], 1.f);
        t[th] = sp(g_crys[c*64 + th] / cn);
    }
    __syncthreads();
    float acc = b_fc[th];
    #pragma unroll 4
    for(int f = 0; f < 64; f++) acc += t[f] * W_fc[f*128 + th];
    hred[th] = sp(acc) * W_out[th];
    __syncthreads();
    for(int o = 64; o > 0; o >>= 1){
        if(th < o) hred[th] += hred[th + o];
        __syncthreads();
    }
    if(th == 0) out[c] = hred[0] + b_out[0];
}

// ---------------- launcher ----------------
extern "C" void kernel_launch(void* const* d_in, const int* in_sizes, int n_in,
                              void* d_out, int out_size){
    const float* atom_fea = (const float*)d_in[0];
    const float* nbr_fea  = (const float*)d_in[1];
    const int*   nbr_idx  = (const int*)  d_in[2];
    const int*   cidx     = (const int*)  d_in[3];
    const float* W_emb    = (const float*)d_in[4];
    const float* b_emb    = (const float*)d_in[5];
    const float* W_full   = (const float*)d_in[6];
    const float* b_full   = (const float*)d_in[7];
    const float* g1       = (const float*)d_in[8];
    const float* be1      = (const float*)d_in[9];
    const float* g2       = (const float*)d_in[10];
    const float* be2      = (const float*)d_in[11];
    const float* W_fc     = (const float*)d_in[12];
    const float* b_fc     = (const float*)d_in[13];
    const float* W_out    = (const float*)d_in[14];
    const float* b_out    = (const float*)d_in[15];
    float* out = (float*)d_out;

    k_emb<<<Nn/8, 512>>>(atom_fea, W_emb, b_emb);

    for(int l = 0; l < 3; l++){
        k_zero_stats<<<1, 256>>>();
        dim3 gp((Nn + 127)/128, 2);
        k_P<<<gp, 512>>>(W_full + (size_t)l*169*128);
        k_Q<<<NM/128, 512>>>(nbr_fea, nbr_idx, W_full + (size_t)l*169*128,
                             b_full + l*128);
        k_fin1<<<1, 128>>>(g1 + l*128, be1 + l*128);
        k_B<<<Nn/32, 256>>>();
        k_fin2<<<1, 64>>>(g2 + l*64, be2 + l*64);
        k_upd<<<(Nn*16)/256, 256>>>();
    }

    k_pool_zero<<<(NCc*Ff + NCc + 255)/256, 256>>>();
    k_pool<<<(Nn*Ff)/256, 256>>>(cidx);
    k_head<<<NCc, 128>>>(W_fc, b_fc, W_out, b_out, out);
}

// round 4
// speedup vs baseline: 1.1205x; 1.1205x over previous
#include <cuda_runtime.h>
#include <math.h>

#define Nn 60000
#define Mm 12
#define F0k 92
#define FBk 41
#define Ff 64
#define Hh 128
#define NCc 2000
#define F2 128
#define NM (Nn*Mm)

typedef unsigned long long u64;

// ---------------- f32x2 packed-FMA helpers (sm_100+ PTX) ----------------
__device__ __forceinline__ u64 ffma2(u64 a, u64 b, u64 c){
    u64 d;
    asm("fma.rn.f32x2 %0, %1, %2, %3;" : "=l"(d) : "l"(a), "l"(b), "l"(c));
    return d;
}
__device__ __forceinline__ u64 dup2(float x){
    u64 d; unsigned xi = __float_as_uint(x);
    asm("mov.b64 %0, {%1, %1};" : "=l"(d) : "r"(xi));
    return d;
}
__device__ __forceinline__ float2 unpk(u64 v){
    unsigned lo, hi;
    asm("mov.b64 {%0, %1}, %2;" : "=r"(lo), "=r"(hi) : "l"(v));
    return make_float2(__uint_as_float(lo), __uint_as_float(hi));
}

// ---------------- scratch ----------------
__device__ float g_x[Nn*Ff];
__device__ float g_P[Nn*256];
__device__ float g_gated[(size_t)NM*F2];
__device__ float g_summed[Nn*Ff];
__device__ double g_stats1[2*F2];
__device__ double g_stats2[2*Ff];
__device__ float g_sc1[F2], g_sh1[F2];
__device__ float g_sc2[Ff], g_sh2[Ff];
__device__ float g_crys[NCc*Ff];
__device__ float g_cnt[NCc];

__device__ __forceinline__ float sp(float x){
    return fmaxf(x, 0.f) + __logf(1.f + __expf(-fabsf(x)));
}
__device__ __forceinline__ float sg(float x){
    return __fdividef(1.f, 1.f + __expf(-x));
}

// ---------------- embedding ----------------
__global__ void k_emb(const float* __restrict__ af, const float* __restrict__ W,
                      const float* __restrict__ b){
    __shared__ float s_af[8][F0k];
    int base = blockIdx.x * 8;
    int tid = threadIdx.x;                    // 512
    for(int idx = tid; idx < 8*F0k; idx += 512){
        int a = idx / F0k, k = idx % F0k;
        s_af[a][k] = af[(base+a)*F0k + k];
    }
    __syncthreads();
    int a = tid >> 6, f = tid & 63;
    float acc = b[f];
    #pragma unroll 4
    for(int k = 0; k < F0k; k++) acc += s_af[a][k] * W[k*Ff + f];
    g_x[(base+a)*Ff + f] = acc;
}

__global__ void k_zero_stats(){
    int t = threadIdx.x;
    g_stats1[t] = 0.0;
    if(t < 2*Ff) g_stats2[t] = 0.0;
}

// ---------------- P = x @ [W1 | W2] (128x128 tile, 256 thr, 8x8, f32x2) ----
__global__ void __launch_bounds__(256,2) k_P(const float* __restrict__ Wf){
    __shared__ __align__(16) float Ws[32][128];
    __shared__ __align__(16) float Xt[32][132];
    int half = blockIdx.y;
    int base = blockIdx.x * 128;
    int rem  = Nn - base;
    int tid  = threadIdx.x;                   // 256
    int tx = tid & 15, ty = tid >> 4;

    u64 acc2[8][4];
    #pragma unroll
    for(int r=0;r<8;r++)
        #pragma unroll
        for(int c=0;c<4;c++) acc2[r][c]=0ULL;

    for(int kc = 0; kc < 2; kc++){
        for(int i2 = tid; i2 < 32*128; i2 += 256){
            int kk = i2 >> 7, j = i2 & 127;
            Ws[kk][j] = Wf[(half*64 + kc*32 + kk)*128 + j];
        }
        for(int i2 = tid; i2 < 32*128; i2 += 256){
            int a = i2 >> 5, kk = i2 & 31;
            int atom = base + a; if(atom >= Nn) atom = Nn-1;
            Xt[kk][a] = g_x[atom*64 + kc*32 + kk];
        }
        __syncthreads();
        #pragma unroll 2
        for(int k = 0; k < 32; k++){
            float4 a0 = *(const float4*)&Xt[k][ty*4];
            float4 a1 = *(const float4*)&Xt[k][64 + ty*4];
            ulonglong2 w0 = *(const ulonglong2*)&Ws[k][tx*4];
            ulonglong2 w1 = *(const ulonglong2*)&Ws[k][64 + tx*4];
            u64 bp[4] = {w0.x, w0.y, w1.x, w1.y};
            float av[8] = {a0.x,a0.y,a0.z,a0.w,a1.x,a1.y,a1.z,a1.w};
            #pragma unroll
            for(int r=0;r<8;r++){
                u64 ad = dup2(av[r]);
                #pragma unroll
                for(int c=0;c<4;c++) acc2[r][c] = ffma2(ad, bp[c], acc2[r][c]);
            }
        }
        __syncthreads();
    }
    #pragma unroll
    for(int r=0;r<8;r++){
        int row = (r<4) ? (ty*4+r) : (64 + ty*4 + (r-4));
        if(row < rem){
            float2 v0 = unpk(acc2[r][0]), v1 = unpk(acc2[r][1]);
            float2 v2 = unpk(acc2[r][2]), v3 = unpk(acc2[r][3]);
            float* dst = g_P + (size_t)(base+row)*256 + half*128;
            *(float4*)&dst[tx*4]    = make_float4(v0.x,v0.y,v1.x,v1.y);
            *(float4*)&dst[64+tx*4] = make_float4(v2.x,v2.y,v3.x,v3.y);
        }
    }
}

// ------- edge GEMM + P adds + bias + BN1 stats (256 thr, 8x8, f32x2) -------
__global__ void __launch_bounds__(256,2) k_Q(const float* __restrict__ nbr,
                    const int* __restrict__ idx,
                    const float* __restrict__ Wf, const float* __restrict__ bias){
    __shared__ __align__(16) float Ws[41][128];
    __shared__ __align__(16) float At[41][132];
    __shared__ float reds[128], redss[128];
    int tid = threadIdx.x;                    // 256
    int row0 = blockIdx.x * 128;
    int tx = tid & 15, ty = tid >> 4;
    const float* W3 = Wf + 128*128;

    for(int i2 = tid; i2 < 41*128; i2 += 256){
        int k = i2 >> 7, j = i2 & 127;
        Ws[k][j] = W3[k*128 + j];
    }
    for(int i2 = tid; i2 < 128*41; i2 += 256){
        int r = i2 / 41, k = i2 % 41;
        At[k][r] = nbr[(size_t)(row0 + r)*41 + k];
    }
    if(tid < 128){ reds[tid] = 0.f; redss[tid] = 0.f; }
    __syncthreads();

    u64 acc2[8][4];
    #pragma unroll
    for(int r=0;r<8;r++)
        #pragma unroll
        for(int c=0;c<4;c++) acc2[r][c]=0ULL;

    #pragma unroll 2
    for(int k = 0; k < 41; k++){
        float4 a0 = *(const float4*)&At[k][ty*4];
        float4 a1 = *(const float4*)&At[k][64 + ty*4];
        ulonglong2 w0 = *(const ulonglong2*)&Ws[k][tx*4];
        ulonglong2 w1 = *(const ulonglong2*)&Ws[k][64 + tx*4];
        u64 bp[4] = {w0.x, w0.y, w1.x, w1.y};
        float av[8] = {a0.x,a0.y,a0.z,a0.w,a1.x,a1.y,a1.z,a1.w};
        #pragma unroll
        for(int r=0;r<8;r++){
            u64 ad = dup2(av[r]);
            #pragma unroll
            for(int c=0;c<4;c++) acc2[r][c] = ffma2(ad, bp[c], acc2[r][c]);
        }
    }
    __syncthreads();

    // overlay epilogue data in At storage
    float (*sP1)[128] = (float(*)[128])&At[0][0];        // 12*128 floats
    int*   sIdx       = (int*)(&At[0][0] + 12*128);      // 128 ints
    int a0atom = row0 / Mm;
    for(int j = tid; j < 12*128; j += 256){
        int at = j >> 7, col = j & 127;
        int atom = a0atom + at; if(atom >= Nn) atom = Nn-1;
        sP1[at][col] = g_P[(size_t)atom*256 + col];
    }
    if(tid < 128) sIdx[tid] = idx[row0 + tid];
    __syncthreads();

    float4 bb0 = *(const float4*)&bias[tx*4];
    float4 bb1 = *(const float4*)&bias[64 + tx*4];
    float bj[8] = {bb0.x,bb0.y,bb0.z,bb0.w,bb1.x,bb1.y,bb1.z,bb1.w};

    float s[8], ssq[8];
    #pragma unroll
    for(int c=0;c<8;c++){ s[c]=0.f; ssq[c]=0.f; }

    #pragma unroll
    for(int r=0;r<8;r++){
        int row = (r<4) ? (ty*4+r) : (64 + ty*4 + (r-4));
        int g = row0 + row;
        int irel = (g / Mm) - a0atom;
        int nb = sIdx[row];
        const float* p2p = g_P + (size_t)nb*256 + 128;
        float4 p1a = *(const float4*)&sP1[irel][tx*4];
        float4 p1b = *(const float4*)&sP1[irel][64+tx*4];
        float4 p2a = *(const float4*)&p2p[tx*4];
        float4 p2b = *(const float4*)&p2p[64+tx*4];
        float pv[8] = {p1a.x+p2a.x, p1a.y+p2a.y, p1a.z+p2a.z, p1a.w+p2a.w,
                       p1b.x+p2b.x, p1b.y+p2b.y, p1b.z+p2b.z, p1b.w+p2b.w};
        float2 v0 = unpk(acc2[r][0]), v1 = unpk(acc2[r][1]);
        float2 v2 = unpk(acc2[r][2]), v3 = unpk(acc2[r][3]);
        float am[8] = {v0.x,v0.y,v1.x,v1.y,v2.x,v2.y,v3.x,v3.y};
        float out[8];
        #pragma unroll
        for(int c=0;c<8;c++){
            float v = am[c] + bj[c] + pv[c];
            out[c] = v; s[c] += v; ssq[c] += v*v;
        }
        float* dst = g_gated + (size_t)g*128;
        *(float4*)&dst[tx*4]    = make_float4(out[0],out[1],out[2],out[3]);
        *(float4*)&dst[64+tx*4] = make_float4(out[4],out[5],out[6],out[7]);
    }
    #pragma unroll
    for(int c=0;c<8;c++){
        int col = (c<4) ? (tx*4+c) : (64 + tx*4 + (c-4));
        atomicAdd(&reds [col], s[c]);
        atomicAdd(&redss[col], ssq[c]);
    }
    __syncthreads();
    if(tid < 128){
        atomicAdd(&g_stats1[tid],       (double)reds[tid]);
        atomicAdd(&g_stats1[128 + tid], (double)redss[tid]);
    }
}

__global__ void k_fin1(const float* __restrict__ g1, const float* __restrict__ be1){
    int j = threadIdx.x;                      // 128
    double n = (double)NM;
    double mu = g_stats1[j] / n;
    double var = g_stats1[128 + j] / n - mu*mu;
    float r = rsqrtf((float)var + 1e-5f);
    float sc = g1[j] * r;
    g_sc1[j] = sc;
    g_sh1[j] = be1[j] - (float)mu * sc;
}

// ------- BN1 apply + sigmoid*softplus + sum over M + BN2 stats (float4) ----
__global__ void k_B(){
    __shared__ float rs[64], rss[64];
    int tid = threadIdx.x;                    // 256; 32 atoms/block
    int fg = (tid & 15) * 4;
    int s  = tid >> 4;                        // 0..15, 2 atoms each
    int base = blockIdx.x * 32 + s*2;
    if(tid < 64){ rs[tid] = 0.f; rss[tid] = 0.f; }
    float4 scf = *(const float4*)&g_sc1[fg];
    float4 shf = *(const float4*)&g_sh1[fg];
    float4 scc = *(const float4*)&g_sc1[64+fg];
    float4 shc = *(const float4*)&g_sh1[64+fg];
    float sc_f[4] = {scf.x,scf.y,scf.z,scf.w};
    float sh_f[4] = {shf.x,shf.y,shf.z,shf.w};
    float sc_c[4] = {scc.x,scc.y,scc.z,scc.w};
    float sh_c[4] = {shc.x,shc.y,shc.z,shc.w};
    __syncthreads();

    float ts[4] = {0,0,0,0}, tss[4] = {0,0,0,0};
    #pragma unroll
    for(int a = 0; a < 2; a++){
        int i = base + a;
        const float* gp = g_gated + (size_t)i*Mm*F2;
        float acc[4] = {0,0,0,0};
        #pragma unroll
        for(int m = 0; m < Mm; m++){
            float4 vf = *(const float4*)&gp[m*F2 + fg];
            float4 vc = *(const float4*)&gp[m*F2 + 64 + fg];
            float f0[4] = {vf.x,vf.y,vf.z,vf.w};
            float c0[4] = {vc.x,vc.y,vc.z,vc.w};
            #pragma unroll
            for(int c=0;c<4;c++)
                acc[c] += sg(f0[c]*sc_f[c]+sh_f[c]) * sp(c0[c]*sc_c[c]+sh_c[c]);
        }
        *(float4*)&g_summed[i*64 + fg] = make_float4(acc[0],acc[1],acc[2],acc[3]);
        #pragma unroll
        for(int c=0;c<4;c++){ ts[c] += acc[c]; tss[c] += acc[c]*acc[c]; }
    }
    #pragma unroll
    for(int c=0;c<4;c++){
        atomicAdd(&rs [fg+c], ts[c]);
        atomicAdd(&rss[fg+c], tss[c]);
    }
    __syncthreads();
    if(tid < 64){
        atomicAdd(&g_stats2[tid],      (double)rs[tid]);
        atomicAdd(&g_stats2[64 + tid], (double)rss[tid]);
    }
}

__global__ void k_fin2(const float* __restrict__ g2, const float* __restrict__ be2){
    int j = threadIdx.x;                      // 64
    double n = (double)Nn;
    double mu = g_stats2[j] / n;
    double var = g_stats2[64 + j] / n - mu*mu;
    float r = rsqrtf((float)var + 1e-5f);
    float sc = g2[j] * r;
    g_sc2[j] = sc;
    g_sh2[j] = be2[j] - (float)mu * sc;
}

__global__ void k_upd(){
    int id = blockIdx.x*256 + threadIdx.x;    // N*16 threads (float4 each)
    int fg = (id & 15) * 4;
    float4 xv = *(const float4*)&g_x[id*4];
    float4 sv = *(const float4*)&g_summed[id*4];
    float4 sc = *(const float4*)&g_sc2[fg];
    float4 sh = *(const float4*)&g_sh2[fg];
    float4 o;
    o.x = sp(xv.x + sv.x*sc.x + sh.x);
    o.y = sp(xv.y + sv.y*sc.y + sh.y);
    o.z = sp(xv.z + sv.z*sc.z + sh.z);
    o.w = sp(xv.w + sv.w*sc.w + sh.w);
    *(float4*)&g_x[id*4] = o;
}

// ---------------- pooling + head ----------------
__global__ void k_pool_zero(){
    int id = blockIdx.x*256 + threadIdx.x;
    if(id < NCc*Ff) g_crys[id] = 0.f;
    else if(id < NCc*Ff + NCc) g_cnt[id - NCc*Ff] = 0.f;
}

__global__ void k_pool(const int* __restrict__ cidx){
    int id = blockIdx.x*256 + threadIdx.x;    // N*64 threads
    int i = id >> 6, f = id & 63;
    int c = cidx[i];
    atomicAdd(&g_crys[c*64 + f], g_x[id]);
    if(f == 0) atomicAdd(&g_cnt[c], 1.f);
}

__global__ void k_head(const float* __restrict__ W_fc, const float* __restrict__ b_fc,
                       const float* __restrict__ W_out, const float* __restrict__ b_out,
                       float* __restrict__ out){
    __shared__ float t[64];
    __shared__ float hred[128];
    int c = blockIdx.x, th = threadIdx.x;     // 128
    if(th < 64){
        float cn = fmaxf(g_cnt[c], 1.f);
        t[th] = sp(g_crys[c*64 + th] / cn);
    }
    __syncthreads();
    float acc = b_fc[th];
    #pragma unroll 4
    for(int f = 0; f < 64; f++) acc += t[f] * W_fc[f*128 + th];
    hred[th] = sp(acc) * W_out[th];
    __syncthreads();
    for(int o = 64; o > 0; o >>= 1){
        if(th < o) hred[th] += hred[th + o];
        __syncthreads();
    }
    if(th == 0) out[c] = hred[0] + b_out[0];
}

// ---------------- launcher ----------------
extern "C" void kernel_launch(void* const* d_in, const int* in_sizes, int n_in,
                              void* d_out, int out_size){
    const float* atom_fea = (const float*)d_in[0];
    const float* nbr_fea  = (const float*)d_in[1];
    const int*   nbr_idx  = (const int*)  d_in[2];
    const int*   cidx     = (const int*)  d_in[3];
    const float* W_emb    = (const float*)d_in[4];
    const float* b_emb    = (const float*)d_in[5];
    const float* W_full   = (const float*)d_in[6];
    const float* b_full   = (const float*)d_in[7];
    const float* g1       = (const float*)d_in[8];
    const float* be1      = (const float*)d_in[9];
    const float* g2       = (const float*)d_in[10];
    const float* be2      = (const float*)d_in[11];
    const float* W_fc     = (const float*)d_in[12];
    const float* b_fc     = (const float*)d_in[13];
    const float* W_out    = (const float*)d_in[14];
    const float* b_out    = (const float*)d_in[15];
    float* out = (float*)d_out;

    k_emb<<<Nn/8, 512>>>(atom_fea, W_emb, b_emb);

    for(int l = 0; l < 3; l++){
        k_zero_stats<<<1, 256>>>();
        dim3 gp((Nn + 127)/128, 2);
        k_P<<<gp, 256>>>(W_full + (size_t)l*169*128);
        k_Q<<<NM/128, 256>>>(nbr_fea, nbr_idx, W_full + (size_t)l*169*128,
                             b_full + l*128);
        k_fin1<<<1, 128>>>(g1 + l*128, be1 + l*128);
        k_B<<<Nn/32, 256>>>();
        k_fin2<<<1, 64>>>(g2 + l*64, be2 + l*64);
        k_upd<<<(Nn*16)/256, 256>>>();
    }

    k_pool_zero<<<(NCc*Ff + NCc + 255)/256, 256>>>();
    k_pool<<<(Nn*Ff)/256, 256>>>(cidx);
    k_head<<<NCc, 128>>>(W_fc, b_fc, W_out, b_out, out);
}

// round 5
// speedup vs baseline: 1.1725x; 1.0464x over previous
#include <cuda_runtime.h>
#include <cuda_fp16.h>
#include <math.h>

#define Nn 60000
#define Mm 12
#define F0k 92
#define FBk 41
#define Ff 64
#define Hh 128
#define NCc 2000
#define F2 128
#define NM (Nn*Mm)

typedef unsigned long long u64;

// ---------------- f32x2 packed-FMA helpers (sm_100+ PTX) ----------------
__device__ __forceinline__ u64 ffma2(u64 a, u64 b, u64 c){
    u64 d;
    asm("fma.rn.f32x2 %0, %1, %2, %3;" : "=l"(d) : "l"(a), "l"(b), "l"(c));
    return d;
}
__device__ __forceinline__ u64 dup2(float x){
    u64 d; unsigned xi = __float_as_uint(x);
    asm("mov.b64 %0, {%1, %1};" : "=l"(d) : "r"(xi));
    return d;
}
__device__ __forceinline__ float2 unpk(u64 v){
    unsigned lo, hi;
    asm("mov.b64 {%0, %1}, %2;" : "=r"(lo), "=r"(hi) : "l"(v));
    return make_float2(__uint_as_float(lo), __uint_as_float(hi));
}

// ---------------- scratch ----------------
__device__ float g_x[Nn*Ff];
__device__ float g_P[Nn*256];
__device__ __half g_gatedh[(size_t)NM*F2];        // fp16 gated (~184MB)
__device__ float g_summed[Nn*Ff];
__device__ double g_stats1[2*F2];
__device__ double g_stats2[2*Ff];
__device__ float g_sc1[F2], g_sh1[F2];
__device__ float g_sc2[Ff], g_sh2[Ff];
__device__ float g_crys[NCc*Ff];
__device__ float g_cnt[NCc];

__device__ __forceinline__ float sp(float x){
    return fmaxf(x, 0.f) + __logf(1.f + __expf(-fabsf(x)));
}
__device__ __forceinline__ float sg(float x){
    return __fdividef(1.f, 1.f + __expf(-x));
}

// ---------------- embedding ----------------
__global__ void k_emb(const float* __restrict__ af, const float* __restrict__ W,
                      const float* __restrict__ b){
    __shared__ float s_af[8][F0k];
    int base = blockIdx.x * 8;
    int tid = threadIdx.x;                    // 512
    for(int idx = tid; idx < 8*F0k; idx += 512){
        int a = idx / F0k, k = idx % F0k;
        s_af[a][k] = af[(base+a)*F0k + k];
    }
    __syncthreads();
    int a = tid >> 6, f = tid & 63;
    float acc = b[f];
    #pragma unroll 4
    for(int k = 0; k < F0k; k++) acc += s_af[a][k] * W[k*Ff + f];
    g_x[(base+a)*Ff + f] = acc;
}

__global__ void k_zero_stats(){
    int t = threadIdx.x;
    g_stats1[t] = 0.0;
    if(t < 2*Ff) g_stats2[t] = 0.0;
}

// ---------------- P = x @ [W1 | W2] (128x128 tile, 256 thr, 8x8, f32x2) ----
__global__ void __launch_bounds__(256,2) k_P(const float* __restrict__ Wf){
    __shared__ __align__(16) float Ws[32][128];
    __shared__ __align__(16) float Xt[32][132];
    int half = blockIdx.y;
    int base = blockIdx.x * 128;
    int rem  = Nn - base;
    int tid  = threadIdx.x;                   // 256
    int tx = tid & 15, ty = tid >> 4;

    u64 acc2[8][4];
    #pragma unroll
    for(int r=0;r<8;r++)
        #pragma unroll
        for(int c=0;c<4;c++) acc2[r][c]=0ULL;

    for(int kc = 0; kc < 2; kc++){
        for(int i2 = tid; i2 < 32*128; i2 += 256){
            int kk = i2 >> 7, j = i2 & 127;
            Ws[kk][j] = Wf[(half*64 + kc*32 + kk)*128 + j];
        }
        for(int i2 = tid; i2 < 32*128; i2 += 256){
            int a = i2 >> 5, kk = i2 & 31;
            int atom = base + a; if(atom >= Nn) atom = Nn-1;
            Xt[kk][a] = g_x[atom*64 + kc*32 + kk];
        }
        __syncthreads();
        #pragma unroll 2
        for(int k = 0; k < 32; k++){
            float4 a0 = *(const float4*)&Xt[k][ty*4];
            float4 a1 = *(const float4*)&Xt[k][64 + ty*4];
            ulonglong2 w0 = *(const ulonglong2*)&Ws[k][tx*4];
            ulonglong2 w1 = *(const ulonglong2*)&Ws[k][64 + tx*4];
            u64 bp[4] = {w0.x, w0.y, w1.x, w1.y};
            float av[8] = {a0.x,a0.y,a0.z,a0.w,a1.x,a1.y,a1.z,a1.w};
            #pragma unroll
            for(int r=0;r<8;r++){
                u64 ad = dup2(av[r]);
                #pragma unroll
                for(int c=0;c<4;c++) acc2[r][c] = ffma2(ad, bp[c], acc2[r][c]);
            }
        }
        __syncthreads();
    }
    #pragma unroll
    for(int r=0;r<8;r++){
        int row = (r<4) ? (ty*4+r) : (64 + ty*4 + (r-4));
        if(row < rem){
            float2 v0 = unpk(acc2[r][0]), v1 = unpk(acc2[r][1]);
            float2 v2 = unpk(acc2[r][2]), v3 = unpk(acc2[r][3]);
            float* dst = g_P + (size_t)(base+row)*256 + half*128;
            *(float4*)&dst[tx*4]    = make_float4(v0.x,v0.y,v1.x,v1.y);
            *(float4*)&dst[64+tx*4] = make_float4(v2.x,v2.y,v3.x,v3.y);
        }
    }
}

// ------- edge GEMM + P adds + bias + BN1 stats (256 thr, 8x8, f32x2) -------
__global__ void __launch_bounds__(256,2) k_Q(const float* __restrict__ nbr,
                    const int* __restrict__ idx,
                    const float* __restrict__ Wf, const float* __restrict__ bias){
    __shared__ __align__(16) float Ws[41][128];
    __shared__ __align__(16) float At[41][132];
    __shared__ float reds[128], redss[128];
    int tid = threadIdx.x;                    // 256
    int row0 = blockIdx.x * 128;
    int tx = tid & 15, ty = tid >> 4;
    const float* W3 = Wf + 128*128;

    for(int i2 = tid; i2 < 41*128; i2 += 256){
        int k = i2 >> 7, j = i2 & 127;
        Ws[k][j] = W3[k*128 + j];
    }
    for(int i2 = tid; i2 < 128*41; i2 += 256){
        int r = i2 / 41, k = i2 % 41;
        At[k][r] = nbr[(size_t)(row0 + r)*41 + k];
    }
    if(tid < 128){ reds[tid] = 0.f; redss[tid] = 0.f; }
    __syncthreads();

    u64 acc2[8][4];
    #pragma unroll
    for(int r=0;r<8;r++)
        #pragma unroll
        for(int c=0;c<4;c++) acc2[r][c]=0ULL;

    #pragma unroll 2
    for(int k = 0; k < 41; k++){
        float4 a0 = *(const float4*)&At[k][ty*4];
        float4 a1 = *(const float4*)&At[k][64 + ty*4];
        ulonglong2 w0 = *(const ulonglong2*)&Ws[k][tx*4];
        ulonglong2 w1 = *(const ulonglong2*)&Ws[k][64 + tx*4];
        u64 bp[4] = {w0.x, w0.y, w1.x, w1.y};
        float av[8] = {a0.x,a0.y,a0.z,a0.w,a1.x,a1.y,a1.z,a1.w};
        #pragma unroll
        for(int r=0;r<8;r++){
            u64 ad = dup2(av[r]);
            #pragma unroll
            for(int c=0;c<4;c++) acc2[r][c] = ffma2(ad, bp[c], acc2[r][c]);
        }
    }
    __syncthreads();

    // overlay epilogue data in At storage
    float (*sP1)[128] = (float(*)[128])&At[0][0];        // 12*128 floats
    int*   sIdx       = (int*)(&At[0][0] + 12*128);      // 128 ints
    int a0atom = row0 / Mm;
    for(int j = tid; j < 12*128; j += 256){
        int at = j >> 7, col = j & 127;
        int atom = a0atom + at; if(atom >= Nn) atom = Nn-1;
        sP1[at][col] = g_P[(size_t)atom*256 + col];
    }
    if(tid < 128) sIdx[tid] = idx[row0 + tid];
    __syncthreads();

    float4 bb0 = *(const float4*)&bias[tx*4];
    float4 bb1 = *(const float4*)&bias[64 + tx*4];
    float bj[8] = {bb0.x,bb0.y,bb0.z,bb0.w,bb1.x,bb1.y,bb1.z,bb1.w};

    float s[8], ssq[8];
    #pragma unroll
    for(int c=0;c<8;c++){ s[c]=0.f; ssq[c]=0.f; }

    #pragma unroll
    for(int r=0;r<8;r++){
        int row = (r<4) ? (ty*4+r) : (64 + ty*4 + (r-4));
        int g = row0 + row;
        int irel = (g / Mm) - a0atom;
        int nb = sIdx[row];
        const float* p2p = g_P + (size_t)nb*256 + 128;
        float4 p1a = *(const float4*)&sP1[irel][tx*4];
        float4 p1b = *(const float4*)&sP1[irel][64+tx*4];
        float4 p2a = *(const float4*)&p2p[tx*4];
        float4 p2b = *(const float4*)&p2p[64+tx*4];
        float pv[8] = {p1a.x+p2a.x, p1a.y+p2a.y, p1a.z+p2a.z, p1a.w+p2a.w,
                       p1b.x+p2b.x, p1b.y+p2b.y, p1b.z+p2b.z, p1b.w+p2b.w};
        float2 v0 = unpk(acc2[r][0]), v1 = unpk(acc2[r][1]);
        float2 v2 = unpk(acc2[r][2]), v3 = unpk(acc2[r][3]);
        float am[8] = {v0.x,v0.y,v1.x,v1.y,v2.x,v2.y,v3.x,v3.y};
        float out[8];
        #pragma unroll
        for(int c=0;c<8;c++){
            float v = am[c] + bj[c] + pv[c];
            out[c] = v; s[c] += v; ssq[c] += v*v;
        }
        __half2 h0 = __floats2half2_rn(out[0], out[1]);
        __half2 h1 = __floats2half2_rn(out[2], out[3]);
        __half2 h2v = __floats2half2_rn(out[4], out[5]);
        __half2 h3 = __floats2half2_rn(out[6], out[7]);
        __half* dst = g_gatedh + (size_t)g*128;
        *(uint2*)&dst[tx*4]    = make_uint2(*(unsigned*)&h0, *(unsigned*)&h1);
        *(uint2*)&dst[64+tx*4] = make_uint2(*(unsigned*)&h2v, *(unsigned*)&h3);
    }
    #pragma unroll
    for(int c=0;c<8;c++){
        int col = (c<4) ? (tx*4+c) : (64 + tx*4 + (c-4));
        atomicAdd(&reds [col], s[c]);
        atomicAdd(&redss[col], ssq[c]);
    }
    __syncthreads();
    if(tid < 128){
        atomicAdd(&g_stats1[tid],       (double)reds[tid]);
        atomicAdd(&g_stats1[128 + tid], (double)redss[tid]);
    }
}

__global__ void k_fin1(const float* __restrict__ g1, const float* __restrict__ be1){
    int j = threadIdx.x;                      // 128
    double n = (double)NM;
    double mu = g_stats1[j] / n;
    double var = g_stats1[128 + j] / n - mu*mu;
    float r = rsqrtf((float)var + 1e-5f);
    float sc = g1[j] * r;
    g_sc1[j] = sc;
    g_sh1[j] = be1[j] - (float)mu * sc;
}

// ------- BN1 apply + sigmoid*softplus + sum over M + BN2 stats (fp16 in) ----
__global__ void k_B(){
    __shared__ float rs[64], rss[64];
    int tid = threadIdx.x;                    // 256; 32 atoms/block
    int fg = (tid & 15) * 4;
    int s  = tid >> 4;                        // 0..15, 2 atoms each
    int base = blockIdx.x * 32 + s*2;
    if(tid < 64){ rs[tid] = 0.f; rss[tid] = 0.f; }
    float4 scf = *(const float4*)&g_sc1[fg];
    float4 shf = *(const float4*)&g_sh1[fg];
    float4 scc = *(const float4*)&g_sc1[64+fg];
    float4 shc = *(const float4*)&g_sh1[64+fg];
    float sc_f[4] = {scf.x,scf.y,scf.z,scf.w};
    float sh_f[4] = {shf.x,shf.y,shf.z,shf.w};
    float sc_c[4] = {scc.x,scc.y,scc.z,scc.w};
    float sh_c[4] = {shc.x,shc.y,shc.z,shc.w};
    __syncthreads();

    float ts[4] = {0,0,0,0}, tss[4] = {0,0,0,0};
    #pragma unroll
    for(int a = 0; a < 2; a++){
        int i = base + a;
        const __half* gp = g_gatedh + (size_t)i*Mm*F2;
        float acc[4] = {0,0,0,0};
        #pragma unroll
        for(int m = 0; m < Mm; m++){
            uint2 uf = *(const uint2*)&gp[m*F2 + fg];
            uint2 uc = *(const uint2*)&gp[m*F2 + 64 + fg];
            float2 f01 = __half22float2(*(__half2*)&uf.x);
            float2 f23 = __half22float2(*(__half2*)&uf.y);
            float2 c01 = __half22float2(*(__half2*)&uc.x);
            float2 c23 = __half22float2(*(__half2*)&uc.y);
            float f0[4] = {f01.x, f01.y, f23.x, f23.y};
            float c0[4] = {c01.x, c01.y, c23.x, c23.y};
            #pragma unroll
            for(int c=0;c<4;c++)
                acc[c] += sg(f0[c]*sc_f[c]+sh_f[c]) * sp(c0[c]*sc_c[c]+sh_c[c]);
        }
        *(float4*)&g_summed[i*64 + fg] = make_float4(acc[0],acc[1],acc[2],acc[3]);
        #pragma unroll
        for(int c=0;c<4;c++){ ts[c] += acc[c]; tss[c] += acc[c]*acc[c]; }
    }
    #pragma unroll
    for(int c=0;c<4;c++){
        atomicAdd(&rs [fg+c], ts[c]);
        atomicAdd(&rss[fg+c], tss[c]);
    }
    __syncthreads();
    if(tid < 64){
        atomicAdd(&g_stats2[tid],      (double)rs[tid]);
        atomicAdd(&g_stats2[64 + tid], (double)rss[tid]);
    }
}

__global__ void k_fin2(const float* __restrict__ g2, const float* __restrict__ be2){
    int j = threadIdx.x;                      // 64
    double n = (double)Nn;
    double mu = g_stats2[j] / n;
    double var = g_stats2[64 + j] / n - mu*mu;
    float r = rsqrtf((float)var + 1e-5f);
    float sc = g2[j] * r;
    g_sc2[j] = sc;
    g_sh2[j] = be2[j] - (float)mu * sc;
}

__global__ void k_upd(){
    int id = blockIdx.x*256 + threadIdx.x;    // N*16 threads (float4 each)
    int fg = (id & 15) * 4;
    float4 xv = *(const float4*)&g_x[id*4];
    float4 sv = *(const float4*)&g_summed[id*4];
    float4 sc = *(const float4*)&g_sc2[fg];
    float4 sh = *(const float4*)&g_sh2[fg];
    float4 o;
    o.x = sp(xv.x + sv.x*sc.x + sh.x);
    o.y = sp(xv.y + sv.y*sc.y + sh.y);
    o.z = sp(xv.z + sv.z*sc.z + sh.z);
    o.w = sp(xv.w + sv.w*sc.w + sh.w);
    *(float4*)&g_x[id*4] = o;
}

// ---------------- pooling + head ----------------
__global__ void k_pool_zero(){
    int id = blockIdx.x*256 + threadIdx.x;
    if(id < NCc*Ff) g_crys[id] = 0.f;
    else if(id < NCc*Ff + NCc) g_cnt[id - NCc*Ff] = 0.f;
}

__global__ void k_pool(const int* __restrict__ cidx){
    int id = blockIdx.x*256 + threadIdx.x;    // N*64 threads
    int i = id >> 6, f = id & 63;
    int c = cidx[i];
    atomicAdd(&g_crys[c*64 + f], g_x[id]);
    if(f == 0) atomicAdd(&g_cnt[c], 1.f);
}

__global__ void k_head(const float* __restrict__ W_fc, const float* __restrict__ b_fc,
                       const float* __restrict__ W_out, const float* __restrict__ b_out,
                       float* __restrict__ out){
    __shared__ float t[64];
    __shared__ float hred[128];
    int c = blockIdx.x, th = threadIdx.x;     // 128
    if(th < 64){
        float cn = fmaxf(g_cnt[c], 1.f);
        t[th] = sp(g_crys[c*64 + th] / cn);
    }
    __syncthreads();
    float acc = b_fc[th];
    #pragma unroll 4
    for(int f = 0; f < 64; f++) acc += t[f] * W_fc[f*128 + th];
    hred[th] = sp(acc) * W_out[th];
    __syncthreads();
    for(int o = 64; o > 0; o >>= 1){
        if(th < o) hred[th] += hred[th + o];
        __syncthreads();
    }
    if(th == 0) out[c] = hred[0] + b_out[0];
}

// ---------------- launcher ----------------
extern "C" void kernel_launch(void* const* d_in, const int* in_sizes, int n_in,
                              void* d_out, int out_size){
    const float* atom_fea = (const float*)d_in[0];
    const float* nbr_fea  = (const float*)d_in[1];
    const int*   nbr_idx  = (const int*)  d_in[2];
    const int*   cidx     = (const int*)  d_in[3];
    const float* W_emb    = (const float*)d_in[4];
    const float* b_emb    = (const float*)d_in[5];
    const float* W_full   = (const float*)d_in[6];
    const float* b_full   = (const float*)d_in[7];
    const float* g1       = (const float*)d_in[8];
    const float* be1      = (const float*)d_in[9];
    const float* g2       = (const float*)d_in[10];
    const float* be2      = (const float*)d_in[11];
    const float* W_fc     = (const float*)d_in[12];
    const float* b_fc     = (const float*)d_in[13];
    const float* W_out    = (const float*)d_in[14];
    const float* b_out    = (const float*)d_in[15];
    float* out = (float*)d_out;

    k_emb<<<Nn/8, 512>>>(atom_fea, W_emb, b_emb);

    for(int l = 0; l < 3; l++){
        k_zero_stats<<<1, 256>>>();
        dim3 gp((Nn + 127)/128, 2);
        k_P<<<gp, 256>>>(W_full + (size_t)l*169*128);
        k_Q<<<NM/128, 256>>>(nbr_fea, nbr_idx, W_full + (size_t)l*169*128,
                             b_full + l*128);
        k_fin1<<<1, 128>>>(g1 + l*128, be1 + l*128);
        k_B<<<Nn/32, 256>>>();
        k_fin2<<<1, 64>>>(g2 + l*64, be2 + l*64);
        k_upd<<<(Nn*16)/256, 256>>>();
    }

    k_pool_zero<<<(NCc*Ff + NCc + 255)/256, 256>>>();
    k_pool<<<(Nn*Ff)/256, 256>>>(cidx);
    k_head<<<NCc, 128>>>(W_fc, b_fc, W_out, b_out, out);
}